// round 1
// baseline (speedup 1.0000x reference)
#include <cuda_runtime.h>
#include <cuda_bf16.h>

// ChebyNet on sm_100a.
// Algebra: with LMAX=2, lhat(h) = -A_hat h. So
//   T0 = x, T1 = -AX, T2 = 2*A2X - x   (AX = A_hat x, A2X = A_hat AX)
//   out = x@(M0-M2) - AX@M1 + 2*A2X@M2 + (b@Wd + bd),  Mk = W[k]@Wd
// Pipeline:
//   1) degree histogram + per-dst edge counts (atomics on small arrays)
//   2) exclusive scan of counts -> CSR rowptr (3-kernel scan)
//   3) scatter edges into CSR (col, normalized val)
//   4) SpMM twice (1 warp per dst row, float4 lanes, no atomics)
//   5) tiny precompute of folded weights P[384][40], cvec[40]
//   6) fused GEMM: out[N,40] = [x|AX|A2X] @ P + cvec

#define NN 100000
#define EE 1600000
#define DD 128
#define UU 64
#define CC 40

// -------- scratch (static device globals; no runtime allocation) --------
__device__ float g_deg[NN];
__device__ int   g_cnt[NN];
__device__ int   g_rowptr[NN + 1];
__device__ int   g_cursor[NN];
__device__ int   g_col[EE];
__device__ float g_val[EE];
__device__ float g_AX[(size_t)NN * DD];
__device__ float g_A2X[(size_t)NN * DD];
__device__ float g_P[3 * DD * CC];   // 384 x 40
__device__ float g_cvec[CC];
__device__ int   g_bsum[256];        // scan partials (196 used)

// -------- 1) init --------
__global__ void init_kernel() {
    int i = blockIdx.x * blockDim.x + threadIdx.x;
    if (i < NN) { g_deg[i] = 0.f; g_cnt[i] = 0; }
}

// -------- 2) histogram: deg (weighted) + counts --------
__global__ void hist_kernel(const int* __restrict__ ei, const float* __restrict__ ew) {
    int e = blockIdx.x * blockDim.x + threadIdx.x;
    if (e < EE) {
        int d = ei[EE + e];
        atomicAdd(&g_deg[d], ew[e]);
        atomicAdd(&g_cnt[d], 1);
    }
}

// -------- 3) exclusive scan of g_cnt -> g_rowptr --------
__global__ void scan1_kernel() {
    __shared__ int s[512];
    int t = threadIdx.x;
    int i = blockIdx.x * 512 + t;
    int v = (i < NN) ? g_cnt[i] : 0;
    s[t] = v;
    __syncthreads();
    for (int off = 1; off < 512; off <<= 1) {
        int add = (t >= off) ? s[t - off] : 0;
        __syncthreads();
        s[t] += add;
        __syncthreads();
    }
    if (i < NN) g_rowptr[i] = s[t] - v;           // exclusive within block
    if (t == 511) g_bsum[blockIdx.x] = s[511];    // block total
}

__global__ void scan2_kernel(int nblocks) {
    __shared__ int s[256];
    int t = threadIdx.x;
    int v = (t < nblocks) ? g_bsum[t] : 0;
    s[t] = v;
    __syncthreads();
    for (int off = 1; off < 256; off <<= 1) {
        int add = (t >= off) ? s[t - off] : 0;
        __syncthreads();
        s[t] += add;
        __syncthreads();
    }
    if (t < nblocks) g_bsum[t] = s[t] - v;        // exclusive partials
}

__global__ void scan3_kernel() {
    int i = blockIdx.x * blockDim.x + threadIdx.x;
    if (i < NN) {
        int v = g_rowptr[i] + g_bsum[i >> 9];
        g_rowptr[i] = v;
        g_cursor[i] = v;
    }
    if (i == 0) g_rowptr[NN] = EE;
}

// -------- 4) scatter edges into CSR, with rw normalization baked in --------
__global__ void scatter_kernel(const int* __restrict__ ei, const float* __restrict__ ew) {
    int e = blockIdx.x * blockDim.x + threadIdx.x;
    if (e < EE) {
        int s = ei[e];
        int d = ei[EE + e];
        int p = atomicAdd(&g_cursor[d], 1);
        g_col[p] = s;
        g_val[p] = ew[e] / fmaxf(g_deg[d], 1e-12f);
    }
}

// -------- 5) SpMM: out[r] = sum_{e in row r} val[e] * in[col[e]]  (1 warp/row) --------
__global__ void spmm_kernel(const float4* __restrict__ in, float4* __restrict__ out) {
    int warp = (blockIdx.x * blockDim.x + threadIdx.x) >> 5;
    int lane = threadIdx.x & 31;
    if (warp >= NN) return;
    int beg = g_rowptr[warp];
    int end = g_rowptr[warp + 1];
    float4 a0 = make_float4(0.f, 0.f, 0.f, 0.f);
    float4 a1 = make_float4(0.f, 0.f, 0.f, 0.f);
    int j = beg;
    for (; j + 1 < end; j += 2) {
        int   c0 = __ldg(&g_col[j]);
        int   c1 = __ldg(&g_col[j + 1]);
        float w0 = __ldg(&g_val[j]);
        float w1 = __ldg(&g_val[j + 1]);
        float4 v0 = __ldg(&in[(size_t)c0 * 32 + lane]);
        float4 v1 = __ldg(&in[(size_t)c1 * 32 + lane]);
        a0.x += w0 * v0.x; a0.y += w0 * v0.y; a0.z += w0 * v0.z; a0.w += w0 * v0.w;
        a1.x += w1 * v1.x; a1.y += w1 * v1.y; a1.z += w1 * v1.z; a1.w += w1 * v1.w;
    }
    if (j < end) {
        int   c0 = __ldg(&g_col[j]);
        float w0 = __ldg(&g_val[j]);
        float4 v0 = __ldg(&in[(size_t)c0 * 32 + lane]);
        a0.x += w0 * v0.x; a0.y += w0 * v0.y; a0.z += w0 * v0.z; a0.w += w0 * v0.w;
    }
    a0.x += a1.x; a0.y += a1.y; a0.z += a1.z; a0.w += a1.w;
    out[(size_t)warp * 32 + lane] = a0;
}

// -------- 6) precompute P = [M0-M2; -M1; 2*M2] (384x40) and cvec --------
__global__ void prep_kernel(const float* __restrict__ W, const float* __restrict__ b,
                            const float* __restrict__ Wd, const float* __restrict__ bd) {
    int idx = blockIdx.x * blockDim.x + threadIdx.x;
    if (idx < 3 * DD * CC) {
        int c = idx % CC;
        int dall = idx / CC;
        int k = dall / DD;
        int d = dall % DD;
        const float* w0 = W + 0 * DD * UU + d * UU;
        const float* w1 = W + 1 * DD * UU + d * UU;
        const float* w2 = W + 2 * DD * UU + d * UU;
        float s = 0.f;
        for (int u = 0; u < UU; u++) {
            float wd = Wd[u * CC + c];
            float coef;
            if (k == 0)      coef = w0[u] - w2[u];
            else if (k == 1) coef = -w1[u];
            else             coef = 2.f * w2[u];
            s += coef * wd;
        }
        g_P[idx] = s;
    } else if (idx < 3 * DD * CC + CC) {
        int c = idx - 3 * DD * CC;
        float s = bd[c];
        for (int u = 0; u < UU; u++) s += b[u] * Wd[u * CC + c];
        g_cvec[c] = s;
    }
}

// -------- 7) fused output GEMM: out = [x|AX|A2X] @ P + cvec --------
// Block tile: 128 nodes x 40 cols, 256 threads, 4x5 register micro-tile.
__global__ void final_kernel(const float* __restrict__ x, float* __restrict__ out) {
    __shared__ float Fs[128 * 33];   // 128 nodes x 32 k, padded stride 33
    __shared__ float Ps[32 * 40];    // 32 k x 40 cols
    int tid = threadIdx.x;
    int cg = tid & 7;    // 0..7  -> cols cg*5 .. cg*5+4
    int ng = tid >> 3;   // 0..31 -> nodes ng*4 .. ng*4+3
    int base = blockIdx.x * 128;

    float acc[4][5];
#pragma unroll
    for (int i = 0; i < 4; i++)
#pragma unroll
        for (int j = 0; j < 5; j++) acc[i][j] = 0.f;

    for (int kk = 0; kk < 384; kk += 32) {
        const float* src = (kk < 128) ? x : ((kk < 256) ? g_AX : g_A2X);
        int kd4 = (kk & 127) >> 2;
        const float4* s4 = (const float4*)src;
        // stage 128x32 feature chunk
#pragma unroll
        for (int q = 0; q < 4; q++) {
            int l = tid + 256 * q;          // 0..1023
            int node = l >> 3;
            int d4 = l & 7;
            int gn = base + node;
            float4 v = make_float4(0.f, 0.f, 0.f, 0.f);
            if (gn < NN) v = __ldg(&s4[(size_t)gn * 32 + kd4 + d4]);
            float* fp = &Fs[node * 33 + d4 * 4];
            fp[0] = v.x; fp[1] = v.y; fp[2] = v.z; fp[3] = v.w;
        }
        // stage 32x40 P chunk
#pragma unroll
        for (int q = 0; q < 5; q++) {
            int l = tid + 256 * q;          // 0..1279
            Ps[l] = g_P[kk * 40 + l];
        }
        __syncthreads();
#pragma unroll
        for (int dp = 0; dp < 32; dp++) {
            float f[4], p[5];
#pragma unroll
            for (int i = 0; i < 4; i++) f[i] = Fs[(ng * 4 + i) * 33 + dp];
#pragma unroll
            for (int j = 0; j < 5; j++) p[j] = Ps[dp * 40 + cg * 5 + j];
#pragma unroll
            for (int i = 0; i < 4; i++)
#pragma unroll
                for (int j = 0; j < 5; j++) acc[i][j] += f[i] * p[j];
        }
        __syncthreads();
    }
#pragma unroll
    for (int i = 0; i < 4; i++) {
        int gn = base + ng * 4 + i;
        if (gn < NN) {
#pragma unroll
            for (int j = 0; j < 5; j++)
                out[(size_t)gn * 40 + cg * 5 + j] = acc[i][j] + g_cvec[cg * 5 + j];
        }
    }
}

extern "C" void kernel_launch(void* const* d_in, const int* in_sizes, int n_in,
                              void* d_out, int out_size) {
    const float* x  = (const float*)d_in[0];
    const int*   ei = (const int*)d_in[1];
    const float* ew = (const float*)d_in[2];
    const float* W  = (const float*)d_in[3];
    const float* b  = (const float*)d_in[4];
    const float* Wd = (const float*)d_in[5];
    const float* bd = (const float*)d_in[6];
    float* out = (float*)d_out;

    float4* AX4;  cudaGetSymbolAddress((void**)&AX4,  g_AX);
    float4* A2X4; cudaGetSymbolAddress((void**)&A2X4, g_A2X);

    const int T = 256;
    int nScanBlocks = (NN + 511) / 512;   // 196

    init_kernel<<<(NN + T - 1) / T, T>>>();
    prep_kernel<<<(3 * DD * CC + CC + T - 1) / T, T>>>(W, b, Wd, bd);
    hist_kernel<<<(EE + T - 1) / T, T>>>(ei, ew);
    scan1_kernel<<<nScanBlocks, 512>>>();
    scan2_kernel<<<1, 256>>>(nScanBlocks);
    scan3_kernel<<<(NN + T - 1) / T, T>>>();
    scatter_kernel<<<(EE + T - 1) / T, T>>>(ei, ew);
    spmm_kernel<<<(NN * 32 + T - 1) / T, T>>>((const float4*)x, AX4);
    spmm_kernel<<<(NN * 32 + T - 1) / T, T>>>((const float4*)AX4, A2X4);
    final_kernel<<<(NN + 127) / 128, 256>>>(x, out);
}

// round 2
// speedup vs baseline: 1.1794x; 1.1794x over previous
#include <cuda_runtime.h>
#include <cuda_bf16.h>
#include <cstdint>

// ChebyNet on sm_100a, round 2.
// Algebra: with LMAX=2, lhat(h) = -A_hat h, so
//   out = Y0 + A_hat(Y1 + A_hat*Y2) + cvec
// where Y0 = X@(M0-M2), Y1 = X@(-M1), Y2 = X@(2*M2), Mk = W[k]@Wd  (each [128,40]).
// Pipeline:
//   CSR build (hist/scan/scatter), tf32-split tensor-core GEMM X[N,128]@Q[128,120],
//   two 40-dim SpMM passes with fused epilogues.

#define NN 100000
#define EE 1600000
#define DD 128
#define UU 64
#define CC 40
#define QN 120   // GEMM output cols (3*40)

// -------- scratch --------
__device__ float g_deg[NN];
__device__ int   g_cnt[NN];
__device__ int   g_rowptr[NN + 1];
__device__ int   g_cursor[NN];
__device__ int   g_col[EE];
__device__ float g_val[EE];
__device__ __align__(16) float g_Y0[(size_t)NN * CC];
__device__ __align__(16) float g_Y1[(size_t)NN * CC];
__device__ __align__(16) float g_Y2[(size_t)NN * CC];
__device__ __align__(16) float g_S [(size_t)NN * CC];
__device__ float g_P[DD * QN];          // Q[128][120]
__device__ __align__(16) float g_cvec[CC];
__device__ int   g_bsum[256];

// -------- init --------
__global__ void init_kernel() {
    int i = blockIdx.x * blockDim.x + threadIdx.x;
    if (i < NN) { g_deg[i] = 0.f; g_cnt[i] = 0; }
}

// -------- histogram --------
__global__ void hist_kernel(const int* __restrict__ ei, const float* __restrict__ ew) {
    int e = blockIdx.x * blockDim.x + threadIdx.x;
    if (e < EE) {
        int d = ei[EE + e];
        atomicAdd(&g_deg[d], ew[e]);
        atomicAdd(&g_cnt[d], 1);
    }
}

// -------- scan (3 kernels) --------
__global__ void scan1_kernel() {
    __shared__ int s[512];
    int t = threadIdx.x;
    int i = blockIdx.x * 512 + t;
    int v = (i < NN) ? g_cnt[i] : 0;
    s[t] = v;
    __syncthreads();
    for (int off = 1; off < 512; off <<= 1) {
        int add = (t >= off) ? s[t - off] : 0;
        __syncthreads();
        s[t] += add;
        __syncthreads();
    }
    if (i < NN) g_rowptr[i] = s[t] - v;
    if (t == 511) g_bsum[blockIdx.x] = s[511];
}

__global__ void scan2_kernel(int nblocks) {
    __shared__ int s[256];
    int t = threadIdx.x;
    int v = (t < nblocks) ? g_bsum[t] : 0;
    s[t] = v;
    __syncthreads();
    for (int off = 1; off < 256; off <<= 1) {
        int add = (t >= off) ? s[t - off] : 0;
        __syncthreads();
        s[t] += add;
        __syncthreads();
    }
    if (t < nblocks) g_bsum[t] = s[t] - v;
}

__global__ void scan3_kernel() {
    int i = blockIdx.x * blockDim.x + threadIdx.x;
    if (i < NN) {
        int v = g_rowptr[i] + g_bsum[i >> 9];
        g_rowptr[i] = v;
        g_cursor[i] = v;
    }
    if (i == 0) g_rowptr[NN] = EE;
}

// -------- scatter --------
__global__ void scatter_kernel(const int* __restrict__ ei, const float* __restrict__ ew) {
    int e = blockIdx.x * blockDim.x + threadIdx.x;
    if (e < EE) {
        int s = ei[e];
        int d = ei[EE + e];
        int p = atomicAdd(&g_cursor[d], 1);
        g_col[p] = s;
        g_val[p] = ew[e] / fmaxf(g_deg[d], 1e-12f);
    }
}

// -------- prep: Q[128][120] and cvec --------
__global__ void prep_kernel(const float* __restrict__ W, const float* __restrict__ b,
                            const float* __restrict__ Wd, const float* __restrict__ bd) {
    int idx = blockIdx.x * blockDim.x + threadIdx.x;
    if (idx < DD * QN) {
        int d = idx / QN;
        int n = idx % QN;
        int k = n / CC;
        int c = n % CC;
        const float* w0 = W + 0 * DD * UU + d * UU;
        const float* w1 = W + 1 * DD * UU + d * UU;
        const float* w2 = W + 2 * DD * UU + d * UU;
        float s = 0.f;
        for (int u = 0; u < UU; u++) {
            float wd = Wd[u * CC + c];
            float coef;
            if (k == 0)      coef = w0[u] - w2[u];
            else if (k == 1) coef = -w1[u];
            else             coef = 2.f * w2[u];
            s += coef * wd;
        }
        g_P[idx] = s;
    } else if (idx < DD * QN + CC) {
        int c = idx - DD * QN;
        float s = bd[c];
        for (int u = 0; u < UU; u++) s += b[u] * Wd[u * CC + c];
        g_cvec[c] = s;
    }
}

// -------- tf32 helpers --------
__device__ __forceinline__ void split_tf32(float v, uint32_t& hi, uint32_t& lo) {
    uint32_t h;
    asm("cvt.rna.tf32.f32 %0, %1;" : "=r"(h) : "f"(v));
    float r = v - __uint_as_float(h);
    uint32_t l;
    asm("cvt.rna.tf32.f32 %0, %1;" : "=r"(l) : "f"(r));
    hi = h; lo = l;
}

__device__ __forceinline__ void mma_tf32(float* c, const uint32_t* a, uint32_t b0, uint32_t b1) {
    asm volatile(
        "mma.sync.aligned.m16n8k8.row.col.f32.tf32.tf32.f32 "
        "{%0,%1,%2,%3}, {%4,%5,%6,%7}, {%8,%9}, {%0,%1,%2,%3};\n"
        : "+f"(c[0]), "+f"(c[1]), "+f"(c[2]), "+f"(c[3])
        : "r"(a[0]), "r"(a[1]), "r"(a[2]), "r"(a[3]), "r"(b0), "r"(b1));
}

// -------- GEMM: [Y0|Y1|Y2] = X[N,128] @ Q[128,120] (split-tf32) --------
// Block: 256 threads (8 warps), tile 128(M) x 128(N, 120 used), K chunked by 32.
// Warp grid 4(M) x 2(N); warp tile 32 x 64 = 2 m-tiles x 8 n-tiles of m16n8k8.
__global__ void __launch_bounds__(256) gemm_kernel(const float* __restrict__ x) {
    __shared__ float Xs[128][33];    // stride 33
    __shared__ float Qs[32][132];    // stride 132

    int tid = threadIdx.x;
    int wid = tid >> 5;
    int lane = tid & 31;
    int warpM = wid >> 1;            // 0..3
    int warpN = wid & 1;             // 0..1
    int g = lane >> 2;               // 0..7
    int tg = lane & 3;               // 0..3
    int mbase = blockIdx.x * 128;

    float acc[2][8][4];
#pragma unroll
    for (int mt = 0; mt < 2; mt++)
#pragma unroll
        for (int nt = 0; nt < 8; nt++)
#pragma unroll
            for (int r = 0; r < 4; r++) acc[mt][nt][r] = 0.f;

    for (int kc = 0; kc < 4; kc++) {
        // stage X chunk: 128 rows x 32 cols
#pragma unroll
        for (int q = 0; q < 4; q++) {
            int pos = tid + q * 256;        // 0..1023
            int r = pos >> 3;
            int c4 = pos & 7;
            int grow = mbase + r;
            float4 v = make_float4(0.f, 0.f, 0.f, 0.f);
            if (grow < NN)
                v = __ldg((const float4*)&x[(size_t)grow * DD + kc * 32 + c4 * 4]);
            Xs[r][c4 * 4 + 0] = v.x;
            Xs[r][c4 * 4 + 1] = v.y;
            Xs[r][c4 * 4 + 2] = v.z;
            Xs[r][c4 * 4 + 3] = v.w;
        }
        // stage Q chunk: 32 k-rows x 128 cols (120 real, rest zero)
#pragma unroll
        for (int q = 0; q < 4; q++) {
            int pos = tid + q * 256;        // 0..1023
            int kr = pos >> 5;
            int n4 = pos & 31;
            int n = n4 * 4;
            float4 v = make_float4(0.f, 0.f, 0.f, 0.f);
            if (n < QN)
                v = *(const float4*)&g_P[(kc * 32 + kr) * QN + n];
            *(float4*)&Qs[kr][n] = v;
        }
        __syncthreads();

#pragma unroll
        for (int ks = 0; ks < 4; ks++) {
            int kk = ks * 8;
            uint32_t ahi[2][4], alo[2][4];
#pragma unroll
            for (int mt = 0; mt < 2; mt++) {
                int mr = warpM * 32 + mt * 16;
                float a0 = Xs[mr + g][kk + tg];
                float a1 = Xs[mr + g + 8][kk + tg];
                float a2 = Xs[mr + g][kk + tg + 4];
                float a3 = Xs[mr + g + 8][kk + tg + 4];
                split_tf32(a0, ahi[mt][0], alo[mt][0]);
                split_tf32(a1, ahi[mt][1], alo[mt][1]);
                split_tf32(a2, ahi[mt][2], alo[mt][2]);
                split_tf32(a3, ahi[mt][3], alo[mt][3]);
            }
#pragma unroll
            for (int nt = 0; nt < 8; nt++) {
                int nb = warpN * 64 + nt * 8;
                float b0 = Qs[kk + tg][nb + g];
                float b1 = Qs[kk + tg + 4][nb + g];
                uint32_t bh0, bl0, bh1, bl1;
                split_tf32(b0, bh0, bl0);
                split_tf32(b1, bh1, bl1);
#pragma unroll
                for (int mt = 0; mt < 2; mt++) {
                    mma_tf32(acc[mt][nt], ahi[mt], bh0, bh1);
                    mma_tf32(acc[mt][nt], ahi[mt], bl0, bl1);
                    mma_tf32(acc[mt][nt], alo[mt], bh0, bh1);
                }
            }
        }
        __syncthreads();
    }

    // epilogue: scatter into Y0/Y1/Y2 by column block
#pragma unroll
    for (int mt = 0; mt < 2; mt++) {
#pragma unroll
        for (int nt = 0; nt < 8; nt++) {
            int n = warpN * 64 + nt * 8 + tg * 2;     // even, pair stays in one 40-block
            if (n >= QN) continue;
            int arr = n / CC;
            int j = n - arr * CC;
            float* base = (arr == 0) ? g_Y0 : (arr == 1) ? g_Y1 : g_Y2;
            int row0 = mbase + warpM * 32 + mt * 16 + g;
            int row1 = row0 + 8;
            if (row0 < NN) {
                float2 v = make_float2(acc[mt][nt][0], acc[mt][nt][1]);
                *(float2*)&base[(size_t)row0 * CC + j] = v;
            }
            if (row1 < NN) {
                float2 v = make_float2(acc[mt][nt][2], acc[mt][nt][3]);
                *(float2*)&base[(size_t)row1 * CC + j] = v;
            }
        }
    }
}

// -------- SpMM 40-dim, warp per row, lanes 0..9 own one float4 each --------
// out[r] = add[r] + sum_{e in row r} val[e]*gather[col[e]]  (+ bias if non-null)
__global__ void spmm40_kernel(const float4* __restrict__ gsrc,
                              const float4* __restrict__ addsrc,
                              const float4* __restrict__ bias,
                              float4* __restrict__ out) {
    int warp = (blockIdx.x * blockDim.x + threadIdx.x) >> 5;
    int lane = threadIdx.x & 31;
    if (warp >= NN) return;
    int beg = g_rowptr[warp];
    int end = g_rowptr[warp + 1];
    bool act = lane < 10;
    float4 a0 = make_float4(0.f, 0.f, 0.f, 0.f);
    float4 a1 = make_float4(0.f, 0.f, 0.f, 0.f);
    int j = beg;
    for (; j + 1 < end; j += 2) {
        int   c0 = __ldg(&g_col[j]);
        int   c1 = __ldg(&g_col[j + 1]);
        float w0 = __ldg(&g_val[j]);
        float w1 = __ldg(&g_val[j + 1]);
        if (act) {
            float4 v0 = __ldg(&gsrc[(size_t)c0 * 10 + lane]);
            float4 v1 = __ldg(&gsrc[(size_t)c1 * 10 + lane]);
            a0.x += w0 * v0.x; a0.y += w0 * v0.y; a0.z += w0 * v0.z; a0.w += w0 * v0.w;
            a1.x += w1 * v1.x; a1.y += w1 * v1.y; a1.z += w1 * v1.z; a1.w += w1 * v1.w;
        }
    }
    if (j < end) {
        int   c0 = __ldg(&g_col[j]);
        float w0 = __ldg(&g_val[j]);
        if (act) {
            float4 v0 = __ldg(&gsrc[(size_t)c0 * 10 + lane]);
            a0.x += w0 * v0.x; a0.y += w0 * v0.y; a0.z += w0 * v0.z; a0.w += w0 * v0.w;
        }
    }
    if (act) {
        float4 r = make_float4(a0.x + a1.x, a0.y + a1.y, a0.z + a1.z, a0.w + a1.w);
        float4 ad = __ldg(&addsrc[(size_t)warp * 10 + lane]);
        r.x += ad.x; r.y += ad.y; r.z += ad.z; r.w += ad.w;
        if (bias) {
            float4 bv = __ldg(&bias[lane]);
            r.x += bv.x; r.y += bv.y; r.z += bv.z; r.w += bv.w;
        }
        out[(size_t)warp * 10 + lane] = r;
    }
}

extern "C" void kernel_launch(void* const* d_in, const int* in_sizes, int n_in,
                              void* d_out, int out_size) {
    const float* x  = (const float*)d_in[0];
    const int*   ei = (const int*)d_in[1];
    const float* ew = (const float*)d_in[2];
    const float* W  = (const float*)d_in[3];
    const float* b  = (const float*)d_in[4];
    const float* Wd = (const float*)d_in[5];
    const float* bd = (const float*)d_in[6];
    float* out = (float*)d_out;

    float4 *Y0, *Y1, *Y2, *S, *CV;
    cudaGetSymbolAddress((void**)&Y0, g_Y0);
    cudaGetSymbolAddress((void**)&Y1, g_Y1);
    cudaGetSymbolAddress((void**)&Y2, g_Y2);
    cudaGetSymbolAddress((void**)&S,  g_S);
    cudaGetSymbolAddress((void**)&CV, g_cvec);

    const int T = 256;
    int nScanBlocks = (NN + 511) / 512;   // 196

    init_kernel<<<(NN + T - 1) / T, T>>>();
    prep_kernel<<<(DD * QN + CC + T - 1) / T, T>>>(W, b, Wd, bd);
    hist_kernel<<<(EE + T - 1) / T, T>>>(ei, ew);
    scan1_kernel<<<nScanBlocks, 512>>>();
    scan2_kernel<<<1, 256>>>(nScanBlocks);
    scan3_kernel<<<(NN + T - 1) / T, T>>>();
    scatter_kernel<<<(EE + T - 1) / T, T>>>(ei, ew);
    gemm_kernel<<<(NN + 127) / 128, 256>>>(x);
    // pass 1: S = Y1 + A*Y2
    spmm40_kernel<<<(NN * 32 + T - 1) / T, T>>>(Y2, Y1, (const float4*)nullptr, S);
    // pass 2: out = Y0 + A*S + cvec
    spmm40_kernel<<<(NN * 32 + T - 1) / T, T>>>(S, Y0, CV, (float4*)out);
}

// round 3
// speedup vs baseline: 1.2298x; 1.0427x over previous
#include <cuda_runtime.h>
#include <cuda_bf16.h>
#include <cstdint>

// ChebyNet on sm_100a, round 3.
//   out = Y0 + A_hat(Y1 + A_hat*Y2) + cvec
// where [Y0|Y1|Y2] = X @ Q, Q[128,120] folded from W,Wd (split-tf32 tensor GEMM).
// Round-3 changes: stream-forked capture (CSR build || GEMM), tf32 splits hoisted
// out of the GEMM inner loop (Q pre-split in prep, X pre-split at staging),
// conflict-free smem strides (36 / 136).

#define NN 100000
#define EE 1600000
#define DD 128
#define UU 64
#define CC 40
#define QN 120
#define QP 128   // padded Q cols

// -------- scratch --------
__device__ float g_deg[NN];
__device__ int   g_cnt[NN];
__device__ int   g_rowptr[NN + 1];
__device__ int   g_cursor[NN];
__device__ int   g_col[EE];
__device__ float g_val[EE];
__device__ __align__(16) float g_Y0[(size_t)NN * CC];
__device__ __align__(16) float g_Y1[(size_t)NN * CC];
__device__ __align__(16) float g_Y2[(size_t)NN * CC];
__device__ __align__(16) float g_S [(size_t)NN * CC];
__device__ __align__(16) float g_Qhi[DD * QP];   // pre-split tf32 hi
__device__ __align__(16) float g_Qlo[DD * QP];   // pre-split tf32 lo
__device__ __align__(16) float g_cvec[CC];
__device__ int   g_bsum[256];

// -------- init --------
__global__ void init_kernel() {
    int i = blockIdx.x * blockDim.x + threadIdx.x;
    if (i < NN) { g_deg[i] = 0.f; g_cnt[i] = 0; }
}

// -------- histogram --------
__global__ void hist_kernel(const int* __restrict__ ei, const float* __restrict__ ew) {
    int e = blockIdx.x * blockDim.x + threadIdx.x;
    if (e < EE) {
        int d = ei[EE + e];
        atomicAdd(&g_deg[d], ew[e]);
        atomicAdd(&g_cnt[d], 1);
    }
}

// -------- scan --------
__global__ void scan1_kernel() {
    __shared__ int s[512];
    int t = threadIdx.x;
    int i = blockIdx.x * 512 + t;
    int v = (i < NN) ? g_cnt[i] : 0;
    s[t] = v;
    __syncthreads();
    for (int off = 1; off < 512; off <<= 1) {
        int add = (t >= off) ? s[t - off] : 0;
        __syncthreads();
        s[t] += add;
        __syncthreads();
    }
    if (i < NN) g_rowptr[i] = s[t] - v;
    if (t == 511) g_bsum[blockIdx.x] = s[511];
}

__global__ void scan2_kernel(int nblocks) {
    __shared__ int s[256];
    int t = threadIdx.x;
    int v = (t < nblocks) ? g_bsum[t] : 0;
    s[t] = v;
    __syncthreads();
    for (int off = 1; off < 256; off <<= 1) {
        int add = (t >= off) ? s[t - off] : 0;
        __syncthreads();
        s[t] += add;
        __syncthreads();
    }
    if (t < nblocks) g_bsum[t] = s[t] - v;
}

__global__ void scan3_kernel() {
    int i = blockIdx.x * blockDim.x + threadIdx.x;
    if (i < NN) {
        int v = g_rowptr[i] + g_bsum[i >> 9];
        g_rowptr[i] = v;
        g_cursor[i] = v;
    }
    if (i == 0) g_rowptr[NN] = EE;
}

// -------- scatter --------
__global__ void scatter_kernel(const int* __restrict__ ei, const float* __restrict__ ew) {
    int e = blockIdx.x * blockDim.x + threadIdx.x;
    if (e < EE) {
        int s = ei[e];
        int d = ei[EE + e];
        int p = atomicAdd(&g_cursor[d], 1);
        g_col[p] = s;
        g_val[p] = ew[e] / fmaxf(g_deg[d], 1e-12f);
    }
}

// -------- tf32 split helper --------
__device__ __forceinline__ void split_tf32(float v, float& hi, float& lo) {
    uint32_t h;
    asm("cvt.rna.tf32.f32 %0, %1;" : "=r"(h) : "f"(v));
    float r = v - __uint_as_float(h);
    uint32_t l;
    asm("cvt.rna.tf32.f32 %0, %1;" : "=r"(l) : "f"(r));
    hi = __uint_as_float(h);
    lo = __uint_as_float(l);
}

// -------- prep: Q (pre-split hi/lo, padded) and cvec --------
__global__ void prep_kernel(const float* __restrict__ W, const float* __restrict__ b,
                            const float* __restrict__ Wd, const float* __restrict__ bd) {
    int idx = blockIdx.x * blockDim.x + threadIdx.x;
    if (idx < DD * QP) {
        int d = idx >> 7;
        int n = idx & 127;
        float s = 0.f;
        if (n < QN) {
            int k = n / CC;
            int c = n % CC;
            const float* w0 = W + 0 * DD * UU + d * UU;
            const float* w1 = W + 1 * DD * UU + d * UU;
            const float* w2 = W + 2 * DD * UU + d * UU;
            for (int u = 0; u < UU; u++) {
                float wd = Wd[u * CC + c];
                float coef;
                if (k == 0)      coef = w0[u] - w2[u];
                else if (k == 1) coef = -w1[u];
                else             coef = 2.f * w2[u];
                s += coef * wd;
            }
        }
        float hi, lo;
        split_tf32(s, hi, lo);
        g_Qhi[idx] = hi;
        g_Qlo[idx] = lo;
    } else if (idx < DD * QP + CC) {
        int c = idx - DD * QP;
        float s = bd[c];
        for (int u = 0; u < UU; u++) s += b[u] * Wd[u * CC + c];
        g_cvec[c] = s;
    }
}

__device__ __forceinline__ void mma_tf32(float* c, const uint32_t* a, uint32_t b0, uint32_t b1) {
    asm volatile(
        "mma.sync.aligned.m16n8k8.row.col.f32.tf32.tf32.f32 "
        "{%0,%1,%2,%3}, {%4,%5,%6,%7}, {%8,%9}, {%0,%1,%2,%3};\n"
        : "+f"(c[0]), "+f"(c[1]), "+f"(c[2]), "+f"(c[3])
        : "r"(a[0]), "r"(a[1]), "r"(a[2]), "r"(a[3]), "r"(b0), "r"(b1));
}

// -------- GEMM: [Y0|Y1|Y2] = X[N,128] @ Q[128,120] (split-tf32, pre-split) --------
// 256 threads, tile 128(M) x 128(N), K chunks of 32. Warp grid 4Mx2N, warp tile 32x64.
// Smem: XsHi/XsLo [128][36], QsHi/QsLo [32][136] (dynamic, ~70KB).
#define XS 36
#define QS 136
__global__ void __launch_bounds__(256) gemm_kernel(const float* __restrict__ x) {
    extern __shared__ float sm[];
    float* XsHi = sm;                    // 128*36
    float* XsLo = XsHi + 128 * XS;
    float* QsHi = XsLo + 128 * XS;       // 32*136
    float* QsLo = QsHi + 32 * QS;

    int tid = threadIdx.x;
    int wid = tid >> 5;
    int lane = tid & 31;
    int warpM = wid >> 1;
    int warpN = wid & 1;
    int g = lane >> 2;
    int tg = lane & 3;
    int mbase = blockIdx.x * 128;

    float acc[2][8][4];
#pragma unroll
    for (int mt = 0; mt < 2; mt++)
#pragma unroll
        for (int nt = 0; nt < 8; nt++)
#pragma unroll
            for (int r = 0; r < 4; r++) acc[mt][nt][r] = 0.f;

    for (int kc = 0; kc < 4; kc++) {
        // stage X chunk (pre-split): 128 rows x 32 cols
#pragma unroll
        for (int q = 0; q < 4; q++) {
            int pos = tid + q * 256;        // 0..1023
            int r = pos >> 3;
            int c4 = pos & 7;
            int grow = mbase + r;
            float4 v = make_float4(0.f, 0.f, 0.f, 0.f);
            if (grow < NN)
                v = __ldg((const float4*)&x[(size_t)grow * DD + kc * 32 + c4 * 4]);
            float4 h4, l4;
            split_tf32(v.x, h4.x, l4.x);
            split_tf32(v.y, h4.y, l4.y);
            split_tf32(v.z, h4.z, l4.z);
            split_tf32(v.w, h4.w, l4.w);
            *(float4*)&XsHi[r * XS + c4 * 4] = h4;
            *(float4*)&XsLo[r * XS + c4 * 4] = l4;
        }
        // stage Q chunk (already split): 32 k-rows x 128 cols
#pragma unroll
        for (int q = 0; q < 4; q++) {
            int pos = tid + q * 256;        // 0..1023
            int kr = pos >> 5;
            int n4 = pos & 31;
            *(float4*)&QsHi[kr * QS + n4 * 4] =
                *(const float4*)&g_Qhi[(kc * 32 + kr) * QP + n4 * 4];
            *(float4*)&QsLo[kr * QS + n4 * 4] =
                *(const float4*)&g_Qlo[(kc * 32 + kr) * QP + n4 * 4];
        }
        __syncthreads();

#pragma unroll
        for (int ks = 0; ks < 4; ks++) {
            int kk = ks * 8;
            uint32_t ahi[2][4], alo[2][4];
#pragma unroll
            for (int mt = 0; mt < 2; mt++) {
                int mr = warpM * 32 + mt * 16;
                ahi[mt][0] = __float_as_uint(XsHi[(mr + g) * XS + kk + tg]);
                ahi[mt][1] = __float_as_uint(XsHi[(mr + g + 8) * XS + kk + tg]);
                ahi[mt][2] = __float_as_uint(XsHi[(mr + g) * XS + kk + tg + 4]);
                ahi[mt][3] = __float_as_uint(XsHi[(mr + g + 8) * XS + kk + tg + 4]);
                alo[mt][0] = __float_as_uint(XsLo[(mr + g) * XS + kk + tg]);
                alo[mt][1] = __float_as_uint(XsLo[(mr + g + 8) * XS + kk + tg]);
                alo[mt][2] = __float_as_uint(XsLo[(mr + g) * XS + kk + tg + 4]);
                alo[mt][3] = __float_as_uint(XsLo[(mr + g + 8) * XS + kk + tg + 4]);
            }
#pragma unroll
            for (int nt = 0; nt < 8; nt++) {
                int nb = warpN * 64 + nt * 8;
                uint32_t bh0 = __float_as_uint(QsHi[(kk + tg) * QS + nb + g]);
                uint32_t bh1 = __float_as_uint(QsHi[(kk + tg + 4) * QS + nb + g]);
                uint32_t bl0 = __float_as_uint(QsLo[(kk + tg) * QS + nb + g]);
                uint32_t bl1 = __float_as_uint(QsLo[(kk + tg + 4) * QS + nb + g]);
#pragma unroll
                for (int mt = 0; mt < 2; mt++) {
                    mma_tf32(acc[mt][nt], ahi[mt], bh0, bh1);
                    mma_tf32(acc[mt][nt], ahi[mt], bl0, bl1);
                    mma_tf32(acc[mt][nt], alo[mt], bh0, bh1);
                }
            }
        }
        __syncthreads();
    }

    // epilogue: scatter into Y0/Y1/Y2 by column block
#pragma unroll
    for (int mt = 0; mt < 2; mt++) {
#pragma unroll
        for (int nt = 0; nt < 8; nt++) {
            int n = warpN * 64 + nt * 8 + tg * 2;
            if (n >= QN) continue;
            int arr = n / CC;
            int j = n - arr * CC;
            float* base = (arr == 0) ? g_Y0 : (arr == 1) ? g_Y1 : g_Y2;
            int row0 = mbase + warpM * 32 + mt * 16 + g;
            int row1 = row0 + 8;
            if (row0 < NN) {
                float2 v = make_float2(acc[mt][nt][0], acc[mt][nt][1]);
                *(float2*)&base[(size_t)row0 * CC + j] = v;
            }
            if (row1 < NN) {
                float2 v = make_float2(acc[mt][nt][2], acc[mt][nt][3]);
                *(float2*)&base[(size_t)row1 * CC + j] = v;
            }
        }
    }
}

// -------- SpMM 40-dim, warp per row --------
__global__ void spmm40_kernel(const float4* __restrict__ gsrc,
                              const float4* __restrict__ addsrc,
                              const float4* __restrict__ bias,
                              float4* __restrict__ out) {
    int warp = (blockIdx.x * blockDim.x + threadIdx.x) >> 5;
    int lane = threadIdx.x & 31;
    if (warp >= NN) return;
    int beg = g_rowptr[warp];
    int end = g_rowptr[warp + 1];
    bool act = lane < 10;
    float4 a0 = make_float4(0.f, 0.f, 0.f, 0.f);
    float4 a1 = make_float4(0.f, 0.f, 0.f, 0.f);
    int j = beg;
    for (; j + 1 < end; j += 2) {
        int   c0 = __ldg(&g_col[j]);
        int   c1 = __ldg(&g_col[j + 1]);
        float w0 = __ldg(&g_val[j]);
        float w1 = __ldg(&g_val[j + 1]);
        if (act) {
            float4 v0 = __ldg(&gsrc[(size_t)c0 * 10 + lane]);
            float4 v1 = __ldg(&gsrc[(size_t)c1 * 10 + lane]);
            a0.x += w0 * v0.x; a0.y += w0 * v0.y; a0.z += w0 * v0.z; a0.w += w0 * v0.w;
            a1.x += w1 * v1.x; a1.y += w1 * v1.y; a1.z += w1 * v1.z; a1.w += w1 * v1.w;
        }
    }
    if (j < end) {
        int   c0 = __ldg(&g_col[j]);
        float w0 = __ldg(&g_val[j]);
        if (act) {
            float4 v0 = __ldg(&gsrc[(size_t)c0 * 10 + lane]);
            a0.x += w0 * v0.x; a0.y += w0 * v0.y; a0.z += w0 * v0.z; a0.w += w0 * v0.w;
        }
    }
    if (act) {
        float4 r = make_float4(a0.x + a1.x, a0.y + a1.y, a0.z + a1.z, a0.w + a1.w);
        float4 ad = __ldg(&addsrc[(size_t)warp * 10 + lane]);
        r.x += ad.x; r.y += ad.y; r.z += ad.z; r.w += ad.w;
        if (bias) {
            float4 bv = __ldg(&bias[lane]);
            r.x += bv.x; r.y += bv.y; r.z += bv.z; r.w += bv.w;
        }
        out[(size_t)warp * 10 + lane] = r;
    }
}

extern "C" void kernel_launch(void* const* d_in, const int* in_sizes, int n_in,
                              void* d_out, int out_size) {
    const float* x  = (const float*)d_in[0];
    const int*   ei = (const int*)d_in[1];
    const float* ew = (const float*)d_in[2];
    const float* W  = (const float*)d_in[3];
    const float* b  = (const float*)d_in[4];
    const float* Wd = (const float*)d_in[5];
    const float* bd = (const float*)d_in[6];
    float* out = (float*)d_out;

    float4 *Y0, *Y1, *Y2, *S, *CV;
    cudaGetSymbolAddress((void**)&Y0, g_Y0);
    cudaGetSymbolAddress((void**)&Y1, g_Y1);
    cudaGetSymbolAddress((void**)&Y2, g_Y2);
    cudaGetSymbolAddress((void**)&S,  g_S);
    cudaGetSymbolAddress((void**)&CV, g_cvec);

    const int T = 256;
    int nScanBlocks = (NN + 511) / 512;   // 196
    int gemmSmem = (2 * 128 * XS + 2 * 32 * QS) * (int)sizeof(float);  // ~70KB
    cudaFuncSetAttribute(gemm_kernel, cudaFuncAttributeMaxDynamicSharedMemorySize, gemmSmem);

    // Fork: CSR build on the capture (default) stream, prep+GEMM on s2.
    // Streams/events are created per call (few calls total) and intentionally
    // not destroyed while capture may still be active.
    cudaStream_t s2;
    cudaStreamCreateWithFlags(&s2, cudaStreamNonBlocking);
    cudaEvent_t eFork, eJoin;
    cudaEventCreateWithFlags(&eFork, cudaEventDisableTiming);
    cudaEventCreateWithFlags(&eJoin, cudaEventDisableTiming);

    cudaEventRecord(eFork, 0);
    cudaStreamWaitEvent(s2, eFork, 0);
    prep_kernel<<<(DD * QP + CC + T - 1) / T, T, 0, s2>>>(W, b, Wd, bd);
    gemm_kernel<<<(NN + 127) / 128, 256, gemmSmem, s2>>>(x);
    cudaEventRecord(eJoin, s2);

    init_kernel<<<(NN + T - 1) / T, T>>>();
    hist_kernel<<<(EE + T - 1) / T, T>>>(ei, ew);
    scan1_kernel<<<nScanBlocks, 512>>>();
    scan2_kernel<<<1, 256>>>(nScanBlocks);
    scan3_kernel<<<(NN + T - 1) / T, T>>>();
    scatter_kernel<<<(EE + T - 1) / T, T>>>(ei, ew);

    cudaStreamWaitEvent(0, eJoin, 0);
    // pass 1: S = Y1 + A*Y2
    spmm40_kernel<<<(NN * 32 + T - 1) / T, T>>>(Y2, Y1, (const float4*)nullptr, S);
    // pass 2: out = Y0 + A*S + cvec
    spmm40_kernel<<<(NN * 32 + T - 1) / T, T>>>(S, Y0, CV, (float4*)out);
}